// round 16
// baseline (speedup 1.0000x reference)
#include <cuda_runtime.h>
#include <cuda_fp16.h>
#include <math.h>
#include <stdint.h>

// ---------------- problem constants ----------------
#define BB    32
#define TT    720
#define CC    862
#define MM    4
#define LTOK  866
#define DMOD  512
#define HH    8
#define EH    64
#define FFD   2048
#define PRED  720
#define NROW  (BB * LTOK)        // 27712
#define NPAD  27776              // 217 * 128
#define LAYERS 3
#define TKP   736                // TT padded to 32
#define PRJP  768                // PRED padded to 128
#define QKVD  1536               // fused QKV output width

// ---------------- device scratch ----------------
__device__ __half g_tok [NPAD * TKP];
__device__ float  g_x   [NROW * DMOD];
__device__ __half g_xt  [NPAD * DMOD];
__device__ __half g_qkv [NROW * QKVD];       // fused q|k|v HALF
__device__ __half g_a   [NPAD * DMOD];
__device__ float  g_tmp [NROW * DMOD];       // residual branch fp32
__device__ __half g_ff  [NPAD * FFD];
__device__ float  g_proj[NROW * PRED];
__device__ float  g_mean[BB * CC];
__device__ float  g_std [BB * CC];
__device__ float  g_rstd[BB * CC];
__device__ float  g_qkvb[LAYERS * QKVD];
// half transposed weights: [Dout][K]
__device__ __half g_wemb [DMOD * TKP];
__device__ __half g_wqkv [LAYERS * QKVD * DMOD];
__device__ __half g_wo_t [LAYERS * DMOD * DMOD];
__device__ __half g_wff1 [LAYERS * FFD * DMOD];
__device__ __half g_wff2 [LAYERS * DMOD * FFD];
__device__ __half g_wproj[PRJP * DMOD];

// ---------------- generic transpose-convert body ----------------
__device__ __forceinline__ void cvt_body(const float* __restrict__ src,
                                         __half* __restrict__ dst,
                                         int K, int Dout, int KP, int DP,
                                         int k0, int d0, int tx, int ty,
                                         float tile[32][33]) {
#pragma unroll
    for (int i = 0; i < 4; i++) {
        int k = k0 + ty + i * 8, d = d0 + tx;
        float v = (k < K && d < Dout) ? src[(size_t)k * Dout + d] : 0.f;
        tile[ty + i * 8][tx] = v;
    }
    __syncthreads();
#pragma unroll
    for (int i = 0; i < 4; i++) {
        int d = d0 + ty + i * 8, k = k0 + tx;
        if (d < DP && k < KP)
            dst[(size_t)d * KP + k] = __float2half(tile[tx][ty + i * 8]);
    }
}

__global__ void cvt_w_kernel(const float* __restrict__ src, __half* __restrict__ dst,
                             int K, int Dout, int KP, int DP) {
    __shared__ float tile[32][33];
    cvt_body(src, dst, K, Dout, KP, DP,
             blockIdx.x * 32, blockIdx.y * 32, threadIdx.x, threadIdx.y, tile);
}

__global__ void cvt_sq_kernel(const float* __restrict__ Wq, const float* __restrict__ Wk,
                              const float* __restrict__ Wv, const float* __restrict__ Wo,
                              __half* __restrict__ wqkv, __half* __restrict__ wo_t) {
    __shared__ float tile[32][33];
    int z = blockIdx.z, l = z >> 2, t = z & 3;
    size_t o  = (size_t)l * DMOD * DMOD;
    size_t oq = (size_t)l * QKVD * DMOD;
    const float* src;
    __half* dst;
    if (t == 0)      { src = Wq + o; dst = wqkv + oq; }
    else if (t == 1) { src = Wk + o; dst = wqkv + oq + (size_t)512 * DMOD; }
    else if (t == 2) { src = Wv + o; dst = wqkv + oq + (size_t)1024 * DMOD; }
    else             { src = Wo + o; dst = wo_t + o; }
    cvt_body(src, dst, DMOD, DMOD, DMOD, DMOD,
             blockIdx.x * 32, blockIdx.y * 32, threadIdx.x, threadIdx.y, tile);
}

__global__ void cvt_ff1_kernel(const float* __restrict__ ff1_W, __half* __restrict__ wff1) {
    __shared__ float tile[32][33];
    size_t of = (size_t)blockIdx.z * DMOD * FFD;
    cvt_body(ff1_W + of, wff1 + of, DMOD, FFD, DMOD, FFD,
             blockIdx.x * 32, blockIdx.y * 32, threadIdx.x, threadIdx.y, tile);
}
__global__ void cvt_ff2_kernel(const float* __restrict__ ff2_W, __half* __restrict__ wff2) {
    __shared__ float tile[32][33];
    size_t of = (size_t)blockIdx.z * DMOD * FFD;
    cvt_body(ff2_W + of, wff2 + of, FFD, DMOD, FFD, DMOD,
             blockIdx.x * 32, blockIdx.y * 32, threadIdx.x, threadIdx.y, tile);
}

// ---------------- qkv bias concat (all layers) ----------------
__global__ void qkv_bias_kernel(const float* __restrict__ bq, const float* __restrict__ bk,
                                const float* __restrict__ bv, float* __restrict__ dst) {
    int i = threadIdx.x + blockIdx.x * 512;
    if (i >= LAYERS * QKVD) return;
    int l = i / QKVD, c = i % QKVD;
    float v;
    if (c < 512)       v = bq[l * DMOD + c];
    else if (c < 1024) v = bk[l * DMOD + c - 512];
    else               v = bv[l * DMOD + c - 1024];
    dst[i] = v;
}

// ---------------- RevIN stats ----------------
__global__ void revin_stats_kernel(const float* __restrict__ xe,
                                   float* __restrict__ mean,
                                   float* __restrict__ stdv,
                                   float* __restrict__ rstd) {
    int c = blockIdx.x * 128 + threadIdx.x;
    int b = blockIdx.y;
    if (c >= CC) return;
    const float* p = xe + (size_t)b * TT * CC + c;
    float s = 0.f, q = 0.f;
    for (int t = 0; t < TT; t++) {
        float v = p[(size_t)t * CC];
        s += v; q += v * v;
    }
    float mu  = s * (1.0f / TT);
    float var = q * (1.0f / TT) - mu * mu;
    float sd  = sqrtf(var + 1e-5f);
    int i = b * CC + c;
    mean[i] = mu; stdv[i] = sd; rstd[i] = 1.0f / sd;
}

// ---------------- tok build ----------------
__global__ void build_tok_kernel(const float* __restrict__ xe,
                                 const float* __restrict__ xm,
                                 const float* __restrict__ mean,
                                 const float* __restrict__ rstd,
                                 const float* __restrict__ rw,
                                 const float* __restrict__ rb,
                                 __half* __restrict__ tok) {
    __shared__ float tile[32][33];
    int b  = blockIdx.z;
    int t0 = blockIdx.x * 32;
    int c0 = blockIdx.y * 32;
    int tx = threadIdx.x, ty = threadIdx.y;
#pragma unroll
    for (int i = 0; i < 4; i++) {
        int t = t0 + ty + i * 8;
        int c = c0 + tx;
        float val = 0.f;
        if (t < TT && c < LTOK) {
            if (c < CC) {
                float xv = xe[((size_t)b * TT + t) * CC + c];
                int ii = b * CC + c;
                val = (xv - mean[ii]) * rstd[ii] * rw[c] + rb[c];
            } else {
                val = xm[((size_t)b * TT + t) * MM + (c - CC)];
            }
        }
        tile[ty + i * 8][tx] = val;
    }
    __syncthreads();
#pragma unroll
    for (int i = 0; i < 4; i++) {
        int l = c0 + ty + i * 8;
        int t = t0 + tx;
        if (l < LTOK && t < TKP)
            tok[((size_t)b * LTOK + l) * TKP + t] = __float2half(tile[tx][ty + i * 8]);
    }
}

// ---------------- FP16 GEMM, ldmatrix + cp.async 5-stage, 128x128x32 ----------
#define KTILE 32
#define ASTR  20
#define HSTG  2560
#define STGW  (2 * HSTG)
#define NSTG  5
#define GEMM_SMEM (NSTG * STGW * 4)   // 102400 B

__device__ __forceinline__ void cpa16(uint32_t smaddr, const void* gptr) {
    asm volatile("cp.async.cg.shared.global [%0], [%1], 16;\n"
                 :: "r"(smaddr), "l"(gptr) : "memory");
}

// act: 0 none, 1 sigmoid, 2 gelu, 3 sigmoid-if-col<1024 (fused QKV)
__global__ __launch_bounds__(256, 2)
void gemm_f16(const __half* __restrict__ A, const __half* __restrict__ W,
              const float* __restrict__ bias,
              float* __restrict__ Cf, __half* __restrict__ Ct,
              int N, int K, int Dout, int act) {
    extern __shared__ uint32_t sm[];
    const uint32_t smbase = (uint32_t)__cvta_generic_to_shared(sm);

    const int tid  = threadIdx.x;
    const int lane = tid & 31;
    const int wid  = tid >> 5;
    const int wRow = (wid & 1) * 64;
    const int wCol = (wid >> 1) * 32;
    const int gID  = lane >> 2;
    const int tg   = lane & 3;

    const int row0 = blockIdx.y * 128;
    const int col0 = blockIdx.x * 128;

    const int sRow = tid >> 1;
    const __half* aSrc = A + (size_t)(row0 + sRow) * K + (tid & 1) * 16;
    const __half* bSrc = W + (size_t)(col0 + sRow) * K + (tid & 1) * 16;
    const uint32_t aDst = smbase + (sRow * ASTR + (tid & 1) * 8) * 4;
    const uint32_t bDst = smbase + (HSTG + sRow * ASTR + (tid & 1) * 8) * 4;

    const int lOct  = lane >> 3;
    const int lIdx  = lane & 7;
    const uint32_t aLd0 = smbase +
        ((wRow + lIdx + (lOct & 1) * 8) * ASTR + (lOct >> 1) * 4) * 4;
    const uint32_t bLd0 = smbase + HSTG * 4 +
        ((wCol + (lOct >> 1) * 8 + lIdx) * ASTR + (lOct & 1) * 4) * 4;

    float acc[4][4][4];
#pragma unroll
    for (int i = 0; i < 4; i++)
#pragma unroll
        for (int j = 0; j < 4; j++)
#pragma unroll
            for (int r = 0; r < 4; r++) acc[i][j][r] = 0.f;

    const int nIter = K >> 5;

#define ISSUE(stage, t)                                          \
    {                                                            \
        uint32_t ad = aDst + (stage) * (STGW * 4);               \
        const __half* ag = aSrc + (size_t)(t) * KTILE;           \
        cpa16(ad, ag); cpa16(ad + 16, ag + 8);                   \
        uint32_t bd = bDst + (stage) * (STGW * 4);               \
        const __half* bg = bSrc + (size_t)(t) * KTILE;           \
        cpa16(bd, bg); cpa16(bd + 16, bg + 8);                   \
    }

    ISSUE(0, 0)
    asm volatile("cp.async.commit_group;\n" ::: "memory");
    ISSUE(1, 1)
    asm volatile("cp.async.commit_group;\n" ::: "memory");
    ISSUE(2, 2)
    asm volatile("cp.async.commit_group;\n" ::: "memory");
    ISSUE(3, 3)
    asm volatile("cp.async.commit_group;\n" ::: "memory");

    int bufC = 0;   // compute stage
    int bufI = 4;   // next issue stage
    for (int t = 0; t < nIter; t++) {
        asm volatile("cp.async.wait_group 3;\n" ::: "memory");
        __syncthreads();
        const uint32_t aB = aLd0 + bufC * (STGW * 4);
        const uint32_t bB = bLd0 + bufC * (STGW * 4);
#pragma unroll
        for (int kc = 0; kc < 2; kc++) {
            const uint32_t kOff = kc * 32;
            uint32_t af[4][4];
            uint32_t bf[4][2];
#pragma unroll
            for (int i = 0; i < 4; i++) {
                asm volatile(
                    "ldmatrix.sync.aligned.m8n8.x4.shared.b16 {%0,%1,%2,%3}, [%4];"
                    : "=r"(af[i][0]), "=r"(af[i][1]), "=r"(af[i][2]), "=r"(af[i][3])
                    : "r"(aB + i * (16 * ASTR * 4) + kOff));
            }
#pragma unroll
            for (int jp = 0; jp < 2; jp++) {
                asm volatile(
                    "ldmatrix.sync.aligned.m8n8.x4.shared.b16 {%0,%1,%2,%3}, [%4];"
                    : "=r"(bf[2 * jp][0]), "=r"(bf[2 * jp][1]),
                      "=r"(bf[2 * jp + 1][0]), "=r"(bf[2 * jp + 1][1])
                    : "r"(bB + jp * (16 * ASTR * 4) + kOff));
            }
#pragma unroll
            for (int i = 0; i < 4; i++)
#pragma unroll
                for (int j = 0; j < 4; j++) {
                    asm volatile(
                        "mma.sync.aligned.m16n8k16.row.col.f32.f16.f16.f32 "
                        "{%0,%1,%2,%3}, {%4,%5,%6,%7}, {%8,%9}, {%0,%1,%2,%3};"
                        : "+f"(acc[i][j][0]), "+f"(acc[i][j][1]),
                          "+f"(acc[i][j][2]), "+f"(acc[i][j][3])
                        : "r"(af[i][0]), "r"(af[i][1]), "r"(af[i][2]), "r"(af[i][3]),
                          "r"(bf[j][0]), "r"(bf[j][1]));
                }
        }
        int nt = t + 4;
        if (nt < nIter) ISSUE(bufI, nt)
        asm volatile("cp.async.commit_group;\n" ::: "memory");
        if (++bufC == NSTG) bufC = 0;
        if (++bufI == NSTG) bufI = 0;
    }
#undef ISSUE

    // epilogue
#pragma unroll
    for (int i = 0; i < 4; i++) {
#pragma unroll
        for (int half = 0; half < 2; half++) {
            int r = row0 + wRow + i * 16 + gID + half * 8;
            if (r >= N) continue;
#pragma unroll
            for (int j = 0; j < 4; j++) {
                int col = col0 + wCol + j * 8 + tg * 2;
                if (col >= Dout) continue;
                float v0 = acc[i][j][half * 2 + 0] + bias[col];
                float v1 = acc[i][j][half * 2 + 1] + bias[col + 1];
                bool sig = (act == 1) || (act == 3 && col < 1024);
                if (sig) {
                    v0 = 1.0f / (1.0f + __expf(-v0));
                    v1 = 1.0f / (1.0f + __expf(-v1));
                } else if (act == 2) {
                    v0 = 0.5f * v0 * (1.0f + erff(v0 * 0.70710678118654752f));
                    v1 = 0.5f * v1 * (1.0f + erff(v1 * 0.70710678118654752f));
                }
                if (Cf)
                    *reinterpret_cast<float2*>(Cf + (size_t)r * Dout + col) =
                        make_float2(v0, v1);
                if (Ct)
                    *reinterpret_cast<__half2*>(Ct + (size_t)r * Dout + col) =
                        __floats2half2_rn(v0, v1);
            }
        }
    }
}

// ---------------- flow attention: fused HALF qkv input (stride QKVD) ----------------
#define H2F(x) __half2float(x)
__global__ __launch_bounds__(512)
void attn_kernel(const __half* __restrict__ qkv, __half* __restrict__ out) {
    int b = blockIdx.x >> 3, h = blockIdx.x & 7;
    const __half* qp = qkv + ((size_t)b * LTOK) * QKVD + h * EH;
    const __half* kp = qp + 512;
    const __half* vp = qp + 1024;
    __half*       op = out + ((size_t)b * LTOK) * DMOD + h * EH;
    int tid = threadIdx.x, lane = tid & 31, wid = tid >> 5;
    const float eps = 1e-6f;

    __shared__ float s_nr[LTOK], s_nc[LTOK], s_nrref[LTOK], s_ncref[LTOK];
    __shared__ float s_ksum[EH], s_qsum[EH], s_kns[EH], s_qns[EH];
    __shared__ float s_kv[EH][EH];
    __shared__ float s_pa[8][EH], s_pb[8][EH];
    __shared__ float s_red[16];

    {
        int e = tid & 63, part = tid >> 6;
        float ka = 0.f, qa = 0.f;
        for (int s = part; s < LTOK; s += 8) {
            ka += H2F(kp[(size_t)s * QKVD + e]);
            qa += H2F(qp[(size_t)s * QKVD + e]);
        }
        s_pa[part][e] = ka;
        s_pb[part][e] = qa;
    }
    __syncthreads();
    if (tid < EH) {
        float a = 0.f, bs = 0.f;
#pragma unroll
        for (int p = 0; p < 8; p++) { a += s_pa[p][tid]; bs += s_pb[p][tid]; }
        s_ksum[tid] = a; s_qsum[tid] = bs;
    }
    __syncthreads();

    for (int r = wid; r < LTOK; r += 16) {
        float qv0 = H2F(qp[(size_t)r * QKVD + lane]), qv1 = H2F(qp[(size_t)r * QKVD + lane + 32]);
        float kv0 = H2F(kp[(size_t)r * QKVD + lane]), kv1 = H2F(kp[(size_t)r * QKVD + lane + 32]);
        float dq = (qv0 + eps) * (s_ksum[lane] + eps) + (qv1 + eps) * (s_ksum[lane + 32] + eps);
        float dk = (kv0 + eps) * (s_qsum[lane] + eps) + (kv1 + eps) * (s_qsum[lane + 32] + eps);
        for (int o = 16; o; o >>= 1) {
            dq += __shfl_xor_sync(0xffffffffu, dq, o);
            dk += __shfl_xor_sync(0xffffffffu, dk, o);
        }
        if (lane == 0) { s_nr[r] = 1.0f / dq; s_nc[r] = 1.0f / dk; }
    }
    __syncthreads();

    {
        int e = tid & 63, part = tid >> 6;
        float ka = 0.f, qa = 0.f;
        for (int s = part; s < LTOK; s += 8) {
            ka += H2F(kp[(size_t)s * QKVD + e]) * s_nc[s];
            qa += H2F(qp[(size_t)s * QKVD + e]) * s_nr[s];
        }
        s_pa[part][e] = ka;
        s_pb[part][e] = qa;
    }
    __syncthreads();
    if (tid < EH) {
        float a = 0.f, bs = 0.f;
#pragma unroll
        for (int p = 0; p < 8; p++) { a += s_pa[p][tid]; bs += s_pb[p][tid]; }
        s_kns[tid] = a; s_qns[tid] = bs;
    }
    __syncthreads();

    for (int r = wid; r < LTOK; r += 16) {
        float qv0 = H2F(qp[(size_t)r * QKVD + lane]), qv1 = H2F(qp[(size_t)r * QKVD + lane + 32]);
        float kv0 = H2F(kp[(size_t)r * QKVD + lane]), kv1 = H2F(kp[(size_t)r * QKVD + lane + 32]);
        float dq = (qv0 + eps) * (s_kns[lane] + eps) + (qv1 + eps) * (s_kns[lane + 32] + eps);
        float dk = (kv0 + eps) * (s_qns[lane] + eps) + (kv1 + eps) * (s_qns[lane + 32] + eps);
        for (int o = 16; o; o >>= 1) {
            dq += __shfl_xor_sync(0xffffffffu, dq, o);
            dk += __shfl_xor_sync(0xffffffffu, dk, o);
        }
        if (lane == 0) {
            s_nrref[r] = 1.0f / (1.0f + expf(-dq));
            s_ncref[r] = dk;
        }
    }
    __syncthreads();

    float lmax = -1e30f;
    for (int s = tid; s < LTOK; s += 512) lmax = fmaxf(lmax, s_ncref[s]);
    for (int o = 16; o; o >>= 1) lmax = fmaxf(lmax, __shfl_xor_sync(0xffffffffu, lmax, o));
    if (lane == 0) s_red[wid] = lmax;
    __syncthreads();
    if (tid == 0) {
        float m = s_red[0];
        for (int i = 1; i < 16; i++) m = fmaxf(m, s_red[i]);
        s_red[0] = m;
    }
    __syncthreads();
    lmax = s_red[0];
    __syncthreads();
    float lsum = 0.f;
    for (int s = tid; s < LTOK; s += 512) {
        float ev = expf(s_ncref[s] - lmax);
        s_ncref[s] = ev;
        lsum += ev;
    }
    for (int o = 16; o; o >>= 1) lsum += __shfl_xor_sync(0xffffffffu, lsum, o);
    if (lane == 0) s_red[wid] = lsum;
    __syncthreads();
    if (tid == 0) {
        float m = 0.f;
        for (int i = 0; i < 16; i++) m += s_red[i];
        s_red[0] = m;
    }
    __syncthreads();
    float scl = (float)LTOK / s_red[0];
    __syncthreads();
    for (int s = tid; s < LTOK; s += 512) s_ncref[s] *= scl;
    __syncthreads();

    int e_own = tid >> 3;
    int d0    = (tid & 7) * 8;
    float acc[8];
#pragma unroll
    for (int i = 0; i < 8; i++) acc[i] = 0.f;
    for (int s0 = 0; s0 < LTOK; s0 += 8) {
        {
            int j = tid >> 6, e = tid & 63;
            int s = s0 + j;
            float kk = 0.f, vv = 0.f;
            if (s < LTOK) {
                kk = H2F(kp[(size_t)s * QKVD + e]);
                vv = H2F(vp[(size_t)s * QKVD + e]) * s_ncref[s];
            }
            s_pa[j][e] = kk;
            s_pb[j][e] = vv;
        }
        __syncthreads();
#pragma unroll
        for (int j = 0; j < 8; j++) {
            float ke = s_pa[j][e_own];
#pragma unroll
            for (int i = 0; i < 8; i++) acc[i] += ke * s_pb[j][d0 + i];
        }
        __syncthreads();
    }
#pragma unroll
    for (int i = 0; i < 8; i++) s_kv[e_own][d0 + i] = acc[i];
    __syncthreads();

    for (int r = wid; r < LTOK; r += 16) {
        float qv0 = H2F(qp[(size_t)r * QKVD + lane]);
        float qv1 = H2F(qp[(size_t)r * QKVD + lane + 32]);
        float a0 = 0.f, a1 = 0.f;
#pragma unroll
        for (int e = 0; e < 32; e++) {
            float qe = __shfl_sync(0xffffffffu, qv0, e);
            a0 += qe * s_kv[e][lane];
            a1 += qe * s_kv[e][lane + 32];
        }
#pragma unroll
        for (int e = 0; e < 32; e++) {
            float qe = __shfl_sync(0xffffffffu, qv1, e);
            a0 += qe * s_kv[e + 32][lane];
            a1 += qe * s_kv[e + 32][lane + 32];
        }
        float sc = s_nr[r] * s_nrref[r];
        op[(size_t)r * DMOD + lane]      = __float2half(a0 * sc);
        op[(size_t)r * DMOD + lane + 32] = __float2half(a1 * sc);
    }
}

// ---------------- residual add + LayerNorm (+ half copy), block-per-row ----------
__global__ __launch_bounds__(256)
void add_ln_kernel(float* __restrict__ x, const float* __restrict__ res,
                   const float* __restrict__ w, const float* __restrict__ bb,
                   __half* __restrict__ xt, int useRes, int writeX) {
    __shared__ float s_s[8], s_q[8];
    int row = blockIdx.x, tid = threadIdx.x, lane = tid & 31, wid = tid >> 5;
    size_t base = (size_t)row * DMOD;
    float v0 = x[base + tid], v1 = x[base + tid + 256];
    if (useRes) { v0 += res[base + tid]; v1 += res[base + tid + 256]; }
    float s = v0 + v1, q = v0 * v0 + v1 * v1;
    for (int o = 16; o; o >>= 1) {
        s += __shfl_xor_sync(0xffffffffu, s, o);
        q += __shfl_xor_sync(0xffffffffu, q, o);
    }
    if (lane == 0) { s_s[wid] = s; s_q[wid] = q; }
    __syncthreads();
    if (tid == 0) {
        float ss = 0.f, qq = 0.f;
        for (int i = 0; i < 8; i++) { ss += s_s[i]; qq += s_q[i]; }
        s_s[0] = ss; s_q[0] = qq;
    }
    __syncthreads();
    float mu  = s_s[0] * (1.0f / DMOD);
    float var = s_q[0] * (1.0f / DMOD) - mu * mu;
    float r   = rsqrtf(var + 1e-5f);
    float o0 = (v0 - mu) * r * w[tid] + bb[tid];
    float o1 = (v1 - mu) * r * w[tid + 256] + bb[tid + 256];
    if (writeX) {
        x[base + tid]       = o0;
        x[base + tid + 256] = o1;
    }
    xt[base + tid]       = __float2half(o0);
    xt[base + tid + 256] = __float2half(o1);
}

// ---------------- output: tiled transpose + RevIN denorm ----------------
__global__ void out_kernel(const float* __restrict__ proj,
                           const float* __restrict__ rw, const float* __restrict__ rb,
                           const float* __restrict__ mean, const float* __restrict__ stdv,
                           float* __restrict__ out) {
    __shared__ float tile[32][33];
    int b  = blockIdx.z;
    int c0 = blockIdx.x * 32;
    int t0 = blockIdx.y * 32;
    int tx = threadIdx.x, ty = threadIdx.y;
#pragma unroll
    for (int i = 0; i < 4; i++) {
        int c = c0 + ty + i * 8;
        int t = t0 + tx;
        float val = 0.f;
        if (c < CC && t < PRED)
            val = proj[((size_t)b * LTOK + c) * PRED + t];
        tile[ty + i * 8][tx] = val;
    }
    __syncthreads();
#pragma unroll
    for (int i = 0; i < 4; i++) {
        int t = t0 + ty + i * 8;
        int c = c0 + tx;
        if (t < PRED && c < CC) {
            float p  = tile[tx][ty + i * 8];
            float vv = (p - rb[c]) / (rw[c] + 1e-10f);
            out[((size_t)b * PRED + t) * CC + c] = vv * stdv[b * CC + c] + mean[b * CC + c];
        }
    }
}

// ---------------- host orchestration ----------------
static inline void launch_gemm(const __half* A, const __half* W, const float* bias,
                               float* Cf, __half* Ct, int N, int K, int Dout, int act) {
    dim3 grid((Dout + 127) / 128, (N + 127) / 128);
    gemm_f16<<<grid, 256, GEMM_SMEM>>>(A, W, bias, Cf, Ct, N, K, Dout, act);
}

extern "C" void kernel_launch(void* const* d_in, const int* in_sizes, int n_in,
                              void* d_out, int out_size) {
    const float* x_enc   = (const float*)d_in[0];
    const float* x_mark  = (const float*)d_in[1];
    const float* revin_w = (const float*)d_in[4];
    const float* revin_b = (const float*)d_in[5];
    const float* emb_W   = (const float*)d_in[6];
    const float* emb_b   = (const float*)d_in[7];
    const float* Wq = (const float*)d_in[8],  *bq = (const float*)d_in[9];
    const float* Wk = (const float*)d_in[10], *bk = (const float*)d_in[11];
    const float* Wv = (const float*)d_in[12], *bv = (const float*)d_in[13];
    const float* Wo = (const float*)d_in[14], *bo = (const float*)d_in[15];
    const float* ff1_W = (const float*)d_in[16], *ff1_b = (const float*)d_in[17];
    const float* ff2_W = (const float*)d_in[18], *ff2_b = (const float*)d_in[19];
    const float* ln1_w = (const float*)d_in[20], *ln1_b = (const float*)d_in[21];
    const float* ln2_w = (const float*)d_in[22], *ln2_b = (const float*)d_in[23];
    const float* lnf_w = (const float*)d_in[24], *lnf_b = (const float*)d_in[25];
    const float* proj_W = (const float*)d_in[26], *proj_b = (const float*)d_in[27];

    static int smem_set = 0;
    if (!smem_set) {
        cudaFuncSetAttribute(gemm_f16, cudaFuncAttributeMaxDynamicSharedMemorySize, GEMM_SMEM);
        smem_set = 1;
    }

    __half *tok, *xt, *qkv, *a, *ff;
    float *x, *tmp, *proj, *mean, *stdv, *rstd, *qkvb;
    __half *wemb, *wqkv, *wo_t, *wff1, *wff2, *wproj;
    cudaGetSymbolAddress((void**)&tok,  g_tok);
    cudaGetSymbolAddress((void**)&x,    g_x);
    cudaGetSymbolAddress((void**)&xt,   g_xt);
    cudaGetSymbolAddress((void**)&qkv,  g_qkv);
    cudaGetSymbolAddress((void**)&a,    g_a);
    cudaGetSymbolAddress((void**)&tmp,  g_tmp);
    cudaGetSymbolAddress((void**)&ff,   g_ff);
    cudaGetSymbolAddress((void**)&proj, g_proj);
    cudaGetSymbolAddress((void**)&mean, g_mean);
    cudaGetSymbolAddress((void**)&stdv, g_std);
    cudaGetSymbolAddress((void**)&rstd, g_rstd);
    cudaGetSymbolAddress((void**)&qkvb, g_qkvb);
    cudaGetSymbolAddress((void**)&wemb,  g_wemb);
    cudaGetSymbolAddress((void**)&wqkv,  g_wqkv);
    cudaGetSymbolAddress((void**)&wo_t,  g_wo_t);
    cudaGetSymbolAddress((void**)&wff1,  g_wff1);
    cudaGetSymbolAddress((void**)&wff2,  g_wff2);
    cudaGetSymbolAddress((void**)&wproj, g_wproj);

    dim3 thr(32, 8);
    cvt_w_kernel <<<dim3(TKP / 32, DMOD / 32), thr>>>(emb_W, wemb, TT, DMOD, TKP, DMOD);
    cvt_sq_kernel<<<dim3(DMOD / 32, DMOD / 32, LAYERS * 4), thr>>>(Wq, Wk, Wv, Wo, wqkv, wo_t);
    cvt_ff1_kernel<<<dim3(DMOD / 32, FFD / 32, LAYERS), thr>>>(ff1_W, wff1);
    cvt_ff2_kernel<<<dim3(FFD / 32, DMOD / 32, LAYERS), thr>>>(ff2_W, wff2);
    cvt_w_kernel <<<dim3(DMOD / 32, PRJP / 32), thr>>>(proj_W, wproj, DMOD, PRED, DMOD, PRJP);
    qkv_bias_kernel<<<(LAYERS * QKVD + 511) / 512, 512>>>(bq, bk, bv, qkvb);

    revin_stats_kernel<<<dim3((CC + 127) / 128, BB), 128>>>(x_enc, mean, stdv, rstd);
    {
        dim3 grid(TKP / 32, (LTOK + 31) / 32, BB);
        build_tok_kernel<<<grid, thr>>>(x_enc, x_mark, mean, rstd, revin_w, revin_b, tok);
    }
    launch_gemm(tok, wemb, emb_b, x, xt, NROW, TKP, DMOD, 0);

    for (int l = 0; l < LAYERS; l++) {
        size_t o  = (size_t)l * DMOD * DMOD;
        size_t oq = (size_t)l * QKVD * DMOD;
        launch_gemm(xt, wqkv + oq, qkvb + l * QKVD, nullptr, qkv, NROW, DMOD, QKVD, 3);
        attn_kernel<<<BB * HH, 512>>>(qkv, a);
        launch_gemm(a, wo_t + o, bo + l * DMOD, tmp, nullptr, NROW, DMOD, DMOD, 0);
        add_ln_kernel<<<NROW, 256>>>(x, tmp, ln1_w + l * DMOD, ln1_b + l * DMOD, xt, 1, 1);
        size_t of = (size_t)l * DMOD * FFD;
        launch_gemm(xt, wff1 + of, ff1_b + l * FFD, nullptr, ff, NROW, DMOD, FFD, 2);
        launch_gemm(ff, wff2 + of, ff2_b + l * DMOD, tmp, nullptr, NROW, FFD, DMOD, 0);
        add_ln_kernel<<<NROW, 256>>>(x, tmp, ln2_w + l * DMOD, ln2_b + l * DMOD, xt, 1, 1);
    }
    add_ln_kernel<<<NROW, 256>>>(x, nullptr, lnf_w, lnf_b, xt, 0, 0);
    launch_gemm(xt, wproj, proj_b, proj, nullptr, NROW, DMOD, PRED, 0);
    {
        dim3 grid((CC + 31) / 32, (PRED + 31) / 32, BB);
        out_kernel<<<grid, thr>>>(proj, revin_w, revin_b, mean, stdv, (float*)d_out);
    }
}

// round 17
// speedup vs baseline: 1.0362x; 1.0362x over previous
#include <cuda_runtime.h>
#include <cuda_fp16.h>
#include <math.h>
#include <stdint.h>

// ---------------- problem constants ----------------
#define BB    32
#define TT    720
#define CC    862
#define MM    4
#define LTOK  866
#define DMOD  512
#define HH    8
#define EH    64
#define FFD   2048
#define PRED  720
#define NROW  (BB * LTOK)        // 27712
#define NPAD  27776              // 217 * 128
#define LAYERS 3
#define TKP   736                // TT padded to 32
#define PRJP  768                // PRED padded to 128
#define QKVD  1536               // fused QKV output width

// ---------------- device scratch ----------------
__device__ __half g_tok [NPAD * TKP];
__device__ float  g_x   [NROW * DMOD];
__device__ __half g_xt  [NPAD * DMOD];
__device__ __half g_qkv [NROW * QKVD];       // fused q|k|v HALF
__device__ __half g_a   [NPAD * DMOD];
__device__ float  g_tmp [NROW * DMOD];       // residual branch fp32
__device__ __half g_ff  [NPAD * FFD];
__device__ float  g_proj[NROW * PRED];
__device__ float  g_mean[BB * CC];
__device__ float  g_std [BB * CC];
__device__ float  g_rstd[BB * CC];
__device__ float  g_qkvb[LAYERS * QKVD];
// half transposed weights: [Dout][K]
__device__ __half g_wemb [DMOD * TKP];
__device__ __half g_wqkv [LAYERS * QKVD * DMOD];
__device__ __half g_wo_t [LAYERS * DMOD * DMOD];
__device__ __half g_wff1 [LAYERS * FFD * DMOD];
__device__ __half g_wff2 [LAYERS * DMOD * FFD];
__device__ __half g_wproj[PRJP * DMOD];

// ---------------- generic transpose-convert body ----------------
__device__ __forceinline__ void cvt_body(const float* __restrict__ src,
                                         __half* __restrict__ dst,
                                         int K, int Dout, int KP, int DP,
                                         int k0, int d0, int tx, int ty,
                                         float tile[32][33]) {
#pragma unroll
    for (int i = 0; i < 4; i++) {
        int k = k0 + ty + i * 8, d = d0 + tx;
        float v = (k < K && d < Dout) ? src[(size_t)k * Dout + d] : 0.f;
        tile[ty + i * 8][tx] = v;
    }
    __syncthreads();
#pragma unroll
    for (int i = 0; i < 4; i++) {
        int d = d0 + ty + i * 8, k = k0 + tx;
        if (d < DP && k < KP)
            dst[(size_t)d * KP + k] = __float2half(tile[tx][ty + i * 8]);
    }
}

__global__ void cvt_w_kernel(const float* __restrict__ src, __half* __restrict__ dst,
                             int K, int Dout, int KP, int DP) {
    __shared__ float tile[32][33];
    cvt_body(src, dst, K, Dout, KP, DP,
             blockIdx.x * 32, blockIdx.y * 32, threadIdx.x, threadIdx.y, tile);
}

__global__ void cvt_sq_kernel(const float* __restrict__ Wq, const float* __restrict__ Wk,
                              const float* __restrict__ Wv, const float* __restrict__ Wo,
                              __half* __restrict__ wqkv, __half* __restrict__ wo_t) {
    __shared__ float tile[32][33];
    int z = blockIdx.z, l = z >> 2, t = z & 3;
    size_t o  = (size_t)l * DMOD * DMOD;
    size_t oq = (size_t)l * QKVD * DMOD;
    const float* src;
    __half* dst;
    if (t == 0)      { src = Wq + o; dst = wqkv + oq; }
    else if (t == 1) { src = Wk + o; dst = wqkv + oq + (size_t)512 * DMOD; }
    else if (t == 2) { src = Wv + o; dst = wqkv + oq + (size_t)1024 * DMOD; }
    else             { src = Wo + o; dst = wo_t + o; }
    cvt_body(src, dst, DMOD, DMOD, DMOD, DMOD,
             blockIdx.x * 32, blockIdx.y * 32, threadIdx.x, threadIdx.y, tile);
}

__global__ void cvt_ff1_kernel(const float* __restrict__ ff1_W, __half* __restrict__ wff1) {
    __shared__ float tile[32][33];
    size_t of = (size_t)blockIdx.z * DMOD * FFD;
    cvt_body(ff1_W + of, wff1 + of, DMOD, FFD, DMOD, FFD,
             blockIdx.x * 32, blockIdx.y * 32, threadIdx.x, threadIdx.y, tile);
}
__global__ void cvt_ff2_kernel(const float* __restrict__ ff2_W, __half* __restrict__ wff2) {
    __shared__ float tile[32][33];
    size_t of = (size_t)blockIdx.z * DMOD * FFD;
    cvt_body(ff2_W + of, wff2 + of, FFD, DMOD, FFD, DMOD,
             blockIdx.x * 32, blockIdx.y * 32, threadIdx.x, threadIdx.y, tile);
}

// ---------------- qkv bias concat (all layers) ----------------
__global__ void qkv_bias_kernel(const float* __restrict__ bq, const float* __restrict__ bk,
                                const float* __restrict__ bv, float* __restrict__ dst) {
    int i = threadIdx.x + blockIdx.x * 512;
    if (i >= LAYERS * QKVD) return;
    int l = i / QKVD, c = i % QKVD;
    float v;
    if (c < 512)       v = bq[l * DMOD + c];
    else if (c < 1024) v = bk[l * DMOD + c - 512];
    else               v = bv[l * DMOD + c - 1024];
    dst[i] = v;
}

// ---------------- RevIN stats ----------------
__global__ void revin_stats_kernel(const float* __restrict__ xe,
                                   float* __restrict__ mean,
                                   float* __restrict__ stdv,
                                   float* __restrict__ rstd) {
    int c = blockIdx.x * 128 + threadIdx.x;
    int b = blockIdx.y;
    if (c >= CC) return;
    const float* p = xe + (size_t)b * TT * CC + c;
    float s = 0.f, q = 0.f;
    for (int t = 0; t < TT; t++) {
        float v = p[(size_t)t * CC];
        s += v; q += v * v;
    }
    float mu  = s * (1.0f / TT);
    float var = q * (1.0f / TT) - mu * mu;
    float sd  = sqrtf(var + 1e-5f);
    int i = b * CC + c;
    mean[i] = mu; stdv[i] = sd; rstd[i] = 1.0f / sd;
}

// ---------------- tok build ----------------
__global__ void build_tok_kernel(const float* __restrict__ xe,
                                 const float* __restrict__ xm,
                                 const float* __restrict__ mean,
                                 const float* __restrict__ rstd,
                                 const float* __restrict__ rw,
                                 const float* __restrict__ rb,
                                 __half* __restrict__ tok) {
    __shared__ float tile[32][33];
    int b  = blockIdx.z;
    int t0 = blockIdx.x * 32;
    int c0 = blockIdx.y * 32;
    int tx = threadIdx.x, ty = threadIdx.y;
#pragma unroll
    for (int i = 0; i < 4; i++) {
        int t = t0 + ty + i * 8;
        int c = c0 + tx;
        float val = 0.f;
        if (t < TT && c < LTOK) {
            if (c < CC) {
                float xv = xe[((size_t)b * TT + t) * CC + c];
                int ii = b * CC + c;
                val = (xv - mean[ii]) * rstd[ii] * rw[c] + rb[c];
            } else {
                val = xm[((size_t)b * TT + t) * MM + (c - CC)];
            }
        }
        tile[ty + i * 8][tx] = val;
    }
    __syncthreads();
#pragma unroll
    for (int i = 0; i < 4; i++) {
        int l = c0 + ty + i * 8;
        int t = t0 + tx;
        if (l < LTOK && t < TKP)
            tok[((size_t)b * LTOK + l) * TKP + t] = __float2half(tile[tx][ty + i * 8]);
    }
}

// ---------------- FP16 GEMM, ldmatrix + cp.async 4-stage, 128x128x32 ----------
#define KTILE 32
#define ASTR  20
#define HSTG  2560
#define STGW  (2 * HSTG)
#define NSTG  4
#define GEMM_SMEM (NSTG * STGW * 4)   // 81920 B

__device__ __forceinline__ void cpa16(uint32_t smaddr, const void* gptr) {
    asm volatile("cp.async.cg.shared.global [%0], [%1], 16;\n"
                 :: "r"(smaddr), "l"(gptr) : "memory");
}

// act: 0 none, 1 sigmoid, 2 gelu, 3 sigmoid-if-col<1024 (fused QKV)
__global__ __launch_bounds__(256, 2)
void gemm_f16(const __half* __restrict__ A, const __half* __restrict__ W,
              const float* __restrict__ bias,
              float* __restrict__ Cf, __half* __restrict__ Ct,
              int N, int K, int Dout, int act) {
    extern __shared__ uint32_t sm[];
    const uint32_t smbase = (uint32_t)__cvta_generic_to_shared(sm);

    const int tid  = threadIdx.x;
    const int lane = tid & 31;
    const int wid  = tid >> 5;
    const int wRow = (wid & 1) * 64;
    const int wCol = (wid >> 1) * 32;
    const int gID  = lane >> 2;
    const int tg   = lane & 3;

    const int row0 = blockIdx.y * 128;
    const int col0 = blockIdx.x * 128;

    const int sRow = tid >> 1;
    const __half* aSrc = A + (size_t)(row0 + sRow) * K + (tid & 1) * 16;
    const __half* bSrc = W + (size_t)(col0 + sRow) * K + (tid & 1) * 16;
    const uint32_t aDst = smbase + (sRow * ASTR + (tid & 1) * 8) * 4;
    const uint32_t bDst = smbase + (HSTG + sRow * ASTR + (tid & 1) * 8) * 4;

    const int lOct  = lane >> 3;
    const int lIdx  = lane & 7;
    const uint32_t aLd0 = smbase +
        ((wRow + lIdx + (lOct & 1) * 8) * ASTR + (lOct >> 1) * 4) * 4;
    const uint32_t bLd0 = smbase + HSTG * 4 +
        ((wCol + (lOct >> 1) * 8 + lIdx) * ASTR + (lOct & 1) * 4) * 4;

    float acc[4][4][4];
#pragma unroll
    for (int i = 0; i < 4; i++)
#pragma unroll
        for (int j = 0; j < 4; j++)
#pragma unroll
            for (int r = 0; r < 4; r++) acc[i][j][r] = 0.f;

    const int nIter = K >> 5;

#define ISSUE(stage, t)                                          \
    {                                                            \
        uint32_t ad = aDst + (stage) * (STGW * 4);               \
        const __half* ag = aSrc + (size_t)(t) * KTILE;           \
        cpa16(ad, ag); cpa16(ad + 16, ag + 8);                   \
        uint32_t bd = bDst + (stage) * (STGW * 4);               \
        const __half* bg = bSrc + (size_t)(t) * KTILE;           \
        cpa16(bd, bg); cpa16(bd + 16, bg + 8);                   \
    }

    ISSUE(0, 0)
    asm volatile("cp.async.commit_group;\n" ::: "memory");
    if (nIter > 1) ISSUE(1, 1)
    asm volatile("cp.async.commit_group;\n" ::: "memory");
    if (nIter > 2) ISSUE(2, 2)
    asm volatile("cp.async.commit_group;\n" ::: "memory");

    for (int t = 0; t < nIter; t++) {
        asm volatile("cp.async.wait_group 2;\n" ::: "memory");
        __syncthreads();
        const int buf = t & 3;
        const uint32_t aB = aLd0 + buf * (STGW * 4);
        const uint32_t bB = bLd0 + buf * (STGW * 4);
#pragma unroll
        for (int kc = 0; kc < 2; kc++) {
            const uint32_t kOff = kc * 32;
            uint32_t af[4][4];
            uint32_t bf[4][2];
#pragma unroll
            for (int i = 0; i < 4; i++) {
                asm volatile(
                    "ldmatrix.sync.aligned.m8n8.x4.shared.b16 {%0,%1,%2,%3}, [%4];"
                    : "=r"(af[i][0]), "=r"(af[i][1]), "=r"(af[i][2]), "=r"(af[i][3])
                    : "r"(aB + i * (16 * ASTR * 4) + kOff));
            }
#pragma unroll
            for (int jp = 0; jp < 2; jp++) {
                asm volatile(
                    "ldmatrix.sync.aligned.m8n8.x4.shared.b16 {%0,%1,%2,%3}, [%4];"
                    : "=r"(bf[2 * jp][0]), "=r"(bf[2 * jp][1]),
                      "=r"(bf[2 * jp + 1][0]), "=r"(bf[2 * jp + 1][1])
                    : "r"(bB + jp * (16 * ASTR * 4) + kOff));
            }
#pragma unroll
            for (int i = 0; i < 4; i++)
#pragma unroll
                for (int j = 0; j < 4; j++) {
                    asm volatile(
                        "mma.sync.aligned.m16n8k16.row.col.f32.f16.f16.f32 "
                        "{%0,%1,%2,%3}, {%4,%5,%6,%7}, {%8,%9}, {%0,%1,%2,%3};"
                        : "+f"(acc[i][j][0]), "+f"(acc[i][j][1]),
                          "+f"(acc[i][j][2]), "+f"(acc[i][j][3])
                        : "r"(af[i][0]), "r"(af[i][1]), "r"(af[i][2]), "r"(af[i][3]),
                          "r"(bf[j][0]), "r"(bf[j][1]));
                }
        }
        int nt = t + 3;
        if (nt < nIter) ISSUE(nt & 3, nt)
        asm volatile("cp.async.commit_group;\n" ::: "memory");
    }
#undef ISSUE

    // epilogue
#pragma unroll
    for (int i = 0; i < 4; i++) {
#pragma unroll
        for (int half = 0; half < 2; half++) {
            int r = row0 + wRow + i * 16 + gID + half * 8;
            if (r >= N) continue;
#pragma unroll
            for (int j = 0; j < 4; j++) {
                int col = col0 + wCol + j * 8 + tg * 2;
                if (col >= Dout) continue;
                float v0 = acc[i][j][half * 2 + 0] + bias[col];
                float v1 = acc[i][j][half * 2 + 1] + bias[col + 1];
                bool sig = (act == 1) || (act == 3 && col < 1024);
                if (sig) {
                    v0 = 1.0f / (1.0f + __expf(-v0));
                    v1 = 1.0f / (1.0f + __expf(-v1));
                } else if (act == 2) {
                    v0 = 0.5f * v0 * (1.0f + erff(v0 * 0.70710678118654752f));
                    v1 = 0.5f * v1 * (1.0f + erff(v1 * 0.70710678118654752f));
                }
                if (Cf)
                    *reinterpret_cast<float2*>(Cf + (size_t)r * Dout + col) =
                        make_float2(v0, v1);
                if (Ct)
                    *reinterpret_cast<__half2*>(Ct + (size_t)r * Dout + col) =
                        __floats2half2_rn(v0, v1);
            }
        }
    }
}

// ---------------- flow attention: fused HALF qkv input (stride QKVD) ----------------
#define H2F(x) __half2float(x)
__global__ __launch_bounds__(512)
void attn_kernel(const __half* __restrict__ qkv, __half* __restrict__ out) {
    int b = blockIdx.x >> 3, h = blockIdx.x & 7;
    const __half* qp = qkv + ((size_t)b * LTOK) * QKVD + h * EH;
    const __half* kp = qp + 512;
    const __half* vp = qp + 1024;
    __half*       op = out + ((size_t)b * LTOK) * DMOD + h * EH;
    int tid = threadIdx.x, lane = tid & 31, wid = tid >> 5;
    const float eps = 1e-6f;

    __shared__ float s_nr[LTOK], s_nc[LTOK], s_nrref[LTOK], s_ncref[LTOK];
    __shared__ float s_ksum[EH], s_qsum[EH], s_kns[EH], s_qns[EH];
    __shared__ float s_kv[EH][EH];
    __shared__ float s_pa[8][EH], s_pb[8][EH];
    __shared__ float s_red[16];

    {
        int e = tid & 63, part = tid >> 6;
        float ka = 0.f, qa = 0.f;
        for (int s = part; s < LTOK; s += 8) {
            ka += H2F(kp[(size_t)s * QKVD + e]);
            qa += H2F(qp[(size_t)s * QKVD + e]);
        }
        s_pa[part][e] = ka;
        s_pb[part][e] = qa;
    }
    __syncthreads();
    if (tid < EH) {
        float a = 0.f, bs = 0.f;
#pragma unroll
        for (int p = 0; p < 8; p++) { a += s_pa[p][tid]; bs += s_pb[p][tid]; }
        s_ksum[tid] = a; s_qsum[tid] = bs;
    }
    __syncthreads();

    for (int r = wid; r < LTOK; r += 16) {
        float qv0 = H2F(qp[(size_t)r * QKVD + lane]), qv1 = H2F(qp[(size_t)r * QKVD + lane + 32]);
        float kv0 = H2F(kp[(size_t)r * QKVD + lane]), kv1 = H2F(kp[(size_t)r * QKVD + lane + 32]);
        float dq = (qv0 + eps) * (s_ksum[lane] + eps) + (qv1 + eps) * (s_ksum[lane + 32] + eps);
        float dk = (kv0 + eps) * (s_qsum[lane] + eps) + (kv1 + eps) * (s_qsum[lane + 32] + eps);
        for (int o = 16; o; o >>= 1) {
            dq += __shfl_xor_sync(0xffffffffu, dq, o);
            dk += __shfl_xor_sync(0xffffffffu, dk, o);
        }
        if (lane == 0) { s_nr[r] = 1.0f / dq; s_nc[r] = 1.0f / dk; }
    }
    __syncthreads();

    {
        int e = tid & 63, part = tid >> 6;
        float ka = 0.f, qa = 0.f;
        for (int s = part; s < LTOK; s += 8) {
            ka += H2F(kp[(size_t)s * QKVD + e]) * s_nc[s];
            qa += H2F(qp[(size_t)s * QKVD + e]) * s_nr[s];
        }
        s_pa[part][e] = ka;
        s_pb[part][e] = qa;
    }
    __syncthreads();
    if (tid < EH) {
        float a = 0.f, bs = 0.f;
#pragma unroll
        for (int p = 0; p < 8; p++) { a += s_pa[p][tid]; bs += s_pb[p][tid]; }
        s_kns[tid] = a; s_qns[tid] = bs;
    }
    __syncthreads();

    for (int r = wid; r < LTOK; r += 16) {
        float qv0 = H2F(qp[(size_t)r * QKVD + lane]), qv1 = H2F(qp[(size_t)r * QKVD + lane + 32]);
        float kv0 = H2F(kp[(size_t)r * QKVD + lane]), kv1 = H2F(kp[(size_t)r * QKVD + lane + 32]);
        float dq = (qv0 + eps) * (s_kns[lane] + eps) + (qv1 + eps) * (s_kns[lane + 32] + eps);
        float dk = (kv0 + eps) * (s_qns[lane] + eps) + (kv1 + eps) * (s_qns[lane + 32] + eps);
        for (int o = 16; o; o >>= 1) {
            dq += __shfl_xor_sync(0xffffffffu, dq, o);
            dk += __shfl_xor_sync(0xffffffffu, dk, o);
        }
        if (lane == 0) {
            s_nrref[r] = 1.0f / (1.0f + expf(-dq));
            s_ncref[r] = dk;
        }
    }
    __syncthreads();

    float lmax = -1e30f;
    for (int s = tid; s < LTOK; s += 512) lmax = fmaxf(lmax, s_ncref[s]);
    for (int o = 16; o; o >>= 1) lmax = fmaxf(lmax, __shfl_xor_sync(0xffffffffu, lmax, o));
    if (lane == 0) s_red[wid] = lmax;
    __syncthreads();
    if (tid == 0) {
        float m = s_red[0];
        for (int i = 1; i < 16; i++) m = fmaxf(m, s_red[i]);
        s_red[0] = m;
    }
    __syncthreads();
    lmax = s_red[0];
    __syncthreads();
    float lsum = 0.f;
    for (int s = tid; s < LTOK; s += 512) {
        float ev = expf(s_ncref[s] - lmax);
        s_ncref[s] = ev;
        lsum += ev;
    }
    for (int o = 16; o; o >>= 1) lsum += __shfl_xor_sync(0xffffffffu, lsum, o);
    if (lane == 0) s_red[wid] = lsum;
    __syncthreads();
    if (tid == 0) {
        float m = 0.f;
        for (int i = 0; i < 16; i++) m += s_red[i];
        s_red[0] = m;
    }
    __syncthreads();
    float scl = (float)LTOK / s_red[0];
    __syncthreads();
    for (int s = tid; s < LTOK; s += 512) s_ncref[s] *= scl;
    __syncthreads();

    int e_own = tid >> 3;
    int d0    = (tid & 7) * 8;
    float acc[8];
#pragma unroll
    for (int i = 0; i < 8; i++) acc[i] = 0.f;
    for (int s0 = 0; s0 < LTOK; s0 += 8) {
        {
            int j = tid >> 6, e = tid & 63;
            int s = s0 + j;
            float kk = 0.f, vv = 0.f;
            if (s < LTOK) {
                kk = H2F(kp[(size_t)s * QKVD + e]);
                vv = H2F(vp[(size_t)s * QKVD + e]) * s_ncref[s];
            }
            s_pa[j][e] = kk;
            s_pb[j][e] = vv;
        }
        __syncthreads();
#pragma unroll
        for (int j = 0; j < 8; j++) {
            float ke = s_pa[j][e_own];
#pragma unroll
            for (int i = 0; i < 8; i++) acc[i] += ke * s_pb[j][d0 + i];
        }
        __syncthreads();
    }
#pragma unroll
    for (int i = 0; i < 8; i++) s_kv[e_own][d0 + i] = acc[i];
    __syncthreads();

    for (int r = wid; r < LTOK; r += 16) {
        float qv0 = H2F(qp[(size_t)r * QKVD + lane]);
        float qv1 = H2F(qp[(size_t)r * QKVD + lane + 32]);
        float a0 = 0.f, a1 = 0.f;
#pragma unroll
        for (int e = 0; e < 32; e++) {
            float qe = __shfl_sync(0xffffffffu, qv0, e);
            a0 += qe * s_kv[e][lane];
            a1 += qe * s_kv[e][lane + 32];
        }
#pragma unroll
        for (int e = 0; e < 32; e++) {
            float qe = __shfl_sync(0xffffffffu, qv1, e);
            a0 += qe * s_kv[e + 32][lane];
            a1 += qe * s_kv[e + 32][lane + 32];
        }
        float sc = s_nr[r] * s_nrref[r];
        op[(size_t)r * DMOD + lane]      = __float2half(a0 * sc);
        op[(size_t)r * DMOD + lane + 32] = __float2half(a1 * sc);
    }
}

// ---------------- residual add + LayerNorm (+ half copy), block-per-row ----------
__global__ __launch_bounds__(256)
void add_ln_kernel(float* __restrict__ x, const float* __restrict__ res,
                   const float* __restrict__ w, const float* __restrict__ bb,
                   __half* __restrict__ xt, int useRes, int writeX) {
    __shared__ float s_s[8], s_q[8];
    int row = blockIdx.x, tid = threadIdx.x, lane = tid & 31, wid = tid >> 5;
    size_t base = (size_t)row * DMOD;
    float v0 = x[base + tid], v1 = x[base + tid + 256];
    if (useRes) { v0 += res[base + tid]; v1 += res[base + tid + 256]; }
    float s = v0 + v1, q = v0 * v0 + v1 * v1;
    for (int o = 16; o; o >>= 1) {
        s += __shfl_xor_sync(0xffffffffu, s, o);
        q += __shfl_xor_sync(0xffffffffu, q, o);
    }
    if (lane == 0) { s_s[wid] = s; s_q[wid] = q; }
    __syncthreads();
    if (tid == 0) {
        float ss = 0.f, qq = 0.f;
        for (int i = 0; i < 8; i++) { ss += s_s[i]; qq += s_q[i]; }
        s_s[0] = ss; s_q[0] = qq;
    }
    __syncthreads();
    float mu  = s_s[0] * (1.0f / DMOD);
    float var = s_q[0] * (1.0f / DMOD) - mu * mu;
    float r   = rsqrtf(var + 1e-5f);
    float o0 = (v0 - mu) * r * w[tid] + bb[tid];
    float o1 = (v1 - mu) * r * w[tid + 256] + bb[tid + 256];
    if (writeX) {
        x[base + tid]       = o0;
        x[base + tid + 256] = o1;
    }
    xt[base + tid]       = __float2half(o0);
    xt[base + tid + 256] = __float2half(o1);
}

// ---------------- output: tiled transpose + RevIN denorm ----------------
__global__ void out_kernel(const float* __restrict__ proj,
                           const float* __restrict__ rw, const float* __restrict__ rb,
                           const float* __restrict__ mean, const float* __restrict__ stdv,
                           float* __restrict__ out) {
    __shared__ float tile[32][33];
    int b  = blockIdx.z;
    int c0 = blockIdx.x * 32;
    int t0 = blockIdx.y * 32;
    int tx = threadIdx.x, ty = threadIdx.y;
#pragma unroll
    for (int i = 0; i < 4; i++) {
        int c = c0 + ty + i * 8;
        int t = t0 + tx;
        float val = 0.f;
        if (c < CC && t < PRED)
            val = proj[((size_t)b * LTOK + c) * PRED + t];
        tile[ty + i * 8][tx] = val;
    }
    __syncthreads();
#pragma unroll
    for (int i = 0; i < 4; i++) {
        int t = t0 + ty + i * 8;
        int c = c0 + tx;
        if (t < PRED && c < CC) {
            float p  = tile[tx][ty + i * 8];
            float vv = (p - rb[c]) / (rw[c] + 1e-10f);
            out[((size_t)b * PRED + t) * CC + c] = vv * stdv[b * CC + c] + mean[b * CC + c];
        }
    }
}

// ---------------- host orchestration ----------------
static inline void launch_gemm(const __half* A, const __half* W, const float* bias,
                               float* Cf, __half* Ct, int N, int K, int Dout, int act) {
    dim3 grid((Dout + 127) / 128, (N + 127) / 128);
    gemm_f16<<<grid, 256, GEMM_SMEM>>>(A, W, bias, Cf, Ct, N, K, Dout, act);
}

extern "C" void kernel_launch(void* const* d_in, const int* in_sizes, int n_in,
                              void* d_out, int out_size) {
    const float* x_enc   = (const float*)d_in[0];
    const float* x_mark  = (const float*)d_in[1];
    const float* revin_w = (const float*)d_in[4];
    const float* revin_b = (const float*)d_in[5];
    const float* emb_W   = (const float*)d_in[6];
    const float* emb_b   = (const float*)d_in[7];
    const float* Wq = (const float*)d_in[8],  *bq = (const float*)d_in[9];
    const float* Wk = (const float*)d_in[10], *bk = (const float*)d_in[11];
    const float* Wv = (const float*)d_in[12], *bv = (const float*)d_in[13];
    const float* Wo = (const float*)d_in[14], *bo = (const float*)d_in[15];
    const float* ff1_W = (const float*)d_in[16], *ff1_b = (const float*)d_in[17];
    const float* ff2_W = (const float*)d_in[18], *ff2_b = (const float*)d_in[19];
    const float* ln1_w = (const float*)d_in[20], *ln1_b = (const float*)d_in[21];
    const float* ln2_w = (const float*)d_in[22], *ln2_b = (const float*)d_in[23];
    const float* lnf_w = (const float*)d_in[24], *lnf_b = (const float*)d_in[25];
    const float* proj_W = (const float*)d_in[26], *proj_b = (const float*)d_in[27];

    static int smem_set = 0;
    if (!smem_set) {
        cudaFuncSetAttribute(gemm_f16, cudaFuncAttributeMaxDynamicSharedMemorySize, GEMM_SMEM);
        smem_set = 1;
    }

    __half *tok, *xt, *qkv, *a, *ff;
    float *x, *tmp, *proj, *mean, *stdv, *rstd, *qkvb;
    __half *wemb, *wqkv, *wo_t, *wff1, *wff2, *wproj;
    cudaGetSymbolAddress((void**)&tok,  g_tok);
    cudaGetSymbolAddress((void**)&x,    g_x);
    cudaGetSymbolAddress((void**)&xt,   g_xt);
    cudaGetSymbolAddress((void**)&qkv,  g_qkv);
    cudaGetSymbolAddress((void**)&a,    g_a);
    cudaGetSymbolAddress((void**)&tmp,  g_tmp);
    cudaGetSymbolAddress((void**)&ff,   g_ff);
    cudaGetSymbolAddress((void**)&proj, g_proj);
    cudaGetSymbolAddress((void**)&mean, g_mean);
    cudaGetSymbolAddress((void**)&stdv, g_std);
    cudaGetSymbolAddress((void**)&rstd, g_rstd);
    cudaGetSymbolAddress((void**)&qkvb, g_qkvb);
    cudaGetSymbolAddress((void**)&wemb,  g_wemb);
    cudaGetSymbolAddress((void**)&wqkv,  g_wqkv);
    cudaGetSymbolAddress((void**)&wo_t,  g_wo_t);
    cudaGetSymbolAddress((void**)&wff1,  g_wff1);
    cudaGetSymbolAddress((void**)&wff2,  g_wff2);
    cudaGetSymbolAddress((void**)&wproj, g_wproj);

    dim3 thr(32, 8);
    cvt_w_kernel <<<dim3(TKP / 32, DMOD / 32), thr>>>(emb_W, wemb, TT, DMOD, TKP, DMOD);
    cvt_sq_kernel<<<dim3(DMOD / 32, DMOD / 32, LAYERS * 4), thr>>>(Wq, Wk, Wv, Wo, wqkv, wo_t);
    cvt_ff1_kernel<<<dim3(DMOD / 32, FFD / 32, LAYERS), thr>>>(ff1_W, wff1);
    cvt_ff2_kernel<<<dim3(FFD / 32, DMOD / 32, LAYERS), thr>>>(ff2_W, wff2);
    cvt_w_kernel <<<dim3(DMOD / 32, PRJP / 32), thr>>>(proj_W, wproj, DMOD, PRED, DMOD, PRJP);
    qkv_bias_kernel<<<(LAYERS * QKVD + 511) / 512, 512>>>(bq, bk, bv, qkvb);

    revin_stats_kernel<<<dim3((CC + 127) / 128, BB), 128>>>(x_enc, mean, stdv, rstd);
    {
        dim3 grid(TKP / 32, (LTOK + 31) / 32, BB);
        build_tok_kernel<<<grid, thr>>>(x_enc, x_mark, mean, rstd, revin_w, revin_b, tok);
    }
    launch_gemm(tok, wemb, emb_b, x, xt, NROW, TKP, DMOD, 0);

    for (int l = 0; l < LAYERS; l++) {
        size_t o  = (size_t)l * DMOD * DMOD;
        size_t oq = (size_t)l * QKVD * DMOD;
        launch_gemm(xt, wqkv + oq, qkvb + l * QKVD, nullptr, qkv, NROW, DMOD, QKVD, 3);
        attn_kernel<<<BB * HH, 512>>>(qkv, a);
        launch_gemm(a, wo_t + o, bo + l * DMOD, tmp, nullptr, NROW, DMOD, DMOD, 0);
        add_ln_kernel<<<NROW, 256>>>(x, tmp, ln1_w + l * DMOD, ln1_b + l * DMOD, xt, 1, 1);
        size_t of = (size_t)l * DMOD * FFD;
        launch_gemm(xt, wff1 + of, ff1_b + l * FFD, nullptr, ff, NROW, DMOD, FFD, 2);
        launch_gemm(ff, wff2 + of, ff2_b + l * DMOD, tmp, nullptr, NROW, FFD, DMOD, 0);
        add_ln_kernel<<<NROW, 256>>>(x, tmp, ln2_w + l * DMOD, ln2_b + l * DMOD, xt, 1, 1);
    }
    add_ln_kernel<<<NROW, 256>>>(x, nullptr, lnf_w, lnf_b, xt, 0, 0);
    launch_gemm(xt, wproj, proj_b, proj, nullptr, NROW, DMOD, PRED, 0);
    {
        dim3 grid((CC + 31) / 32, (PRED + 31) / 32, BB);
        out_kernel<<<grid, thr>>>(proj, revin_w, revin_b, mean, stdv, (float*)d_out);
    }
}